// round 16
// baseline (speedup 1.0000x reference)
#include <cuda_runtime.h>
#include <cuda_fp16.h>
#include <cstdint>

#define NN 10000
#define EE 320000
#define HCv 256
#define EDv 64
#define TOT (EE + NN)
#define NTILES ((TOT + 63) / 64)
#define FULLMASK 0xffffffffu

static __device__ __forceinline__ int clampN(int v) {
    v = v < 0 ? 0 : v;
    return v > (NN - 1) ? (NN - 1) : v;
}

static __device__ __forceinline__ uint32_t pack_h2(float x, float y) {
    __half2 h = __floats2half2_rn(x, y);
    return *(uint32_t*)&h;
}

// ---------------- scratch (device globals; no allocations allowed) ----------------
static __device__ float    g_xl[NN * HCv];
static __device__ __half   g_xl_h[NN * HCv];          // fp16 mirror, k_node aggregation only
static __device__ float    g_xr[NN * HCv];
static __device__ float    g_logits[TOT * 4];         // indexed by CSR position
static __device__ float    g_loop_attr[NN * EDv];
static __device__ uint32_t g_WeB_hi[32 * HCv];        // We fp16 (2-term split in logits)
static __device__ uint32_t g_WB_hi[2 * 128 * HCv];
static __device__ uint32_t g_WB_lo[2 * 128 * HCv];
static __device__ int      g_deg[NN];
static __device__ int      g_rowptr[NN + 1];
static __device__ int      g_cursor[NN];
static __device__ int      g_eids[EE];                // CSR pos -> original edge id
static __device__ int      g_esrc[EE];                // CSR pos -> src node
static __device__ int      g_edst[EE];                // CSR pos -> dst node

// ---------------- initA: CSR init + We pack (main stream) ----------------
__global__ void k_initA(const float* __restrict__ We) {
    int i = blockIdx.x * blockDim.x + threadIdx.x;
    if (i < NN) { g_deg[i] = 0; g_cursor[i] = 0; }
    if (i < 32 * HCv) {
        int c = i & 255, k2 = i >> 8;
        float v0 = We[c * 64 + 2 * k2];
        float v1 = We[c * 64 + 2 * k2 + 1];
        g_WeB_hi[k2 * 256 + c] = pack_h2(v0, v1);
    }
}

// ---------------- initB: Wl/Wr pack (forked stream, feeds k_proj_mma) ----------------
__global__ void k_initB(const float* __restrict__ Wl, const float* __restrict__ Wr) {
    int i = blockIdx.x * blockDim.x + threadIdx.x;
    if (i < 2 * 128 * HCv) {
        int w = i >> 15;
        int rem = i & 32767;
        int c = rem & 255, k2 = rem >> 8;
        const float* W = w ? Wr : Wl;
        float v0 = W[c * 256 + 2 * k2];
        float v1 = W[c * 256 + 2 * k2 + 1];
        __half h0 = __float2half_rn(v0), h1 = __float2half_rn(v1);
        g_WB_hi[i] = pack_h2(__half2float(h0), __half2float(h1));
        g_WB_lo[i] = pack_h2(v0 - __half2float(h0), v1 - __half2float(h1));
    }
}

__global__ void k_count(const int* __restrict__ ei) {
    int e = blockIdx.x * blockDim.x + threadIdx.x;
    if (e < EE) atomicAdd(&g_deg[clampN(ei[EE + e])], 1);
}

__global__ void k_scan() {
    __shared__ int part[1024];
    int t = threadIdx.x;
    int base = t * 10;
    int pre[10];
    int s = 0;
#pragma unroll
    for (int j = 0; j < 10; j++) {
        int idx = base + j;
        int v = (idx < NN) ? g_deg[idx] : 0;
        pre[j] = s;
        s += v;
    }
    part[t] = s;
    __syncthreads();
    for (int off = 1; off < 1024; off <<= 1) {
        int y = (t >= off) ? part[t - off] : 0;
        __syncthreads();
        part[t] += y;
        __syncthreads();
    }
    int excl = (t == 0) ? 0 : part[t - 1];
#pragma unroll
    for (int j = 0; j < 10; j++) {
        int idx = base + j;
        if (idx < NN) g_rowptr[idx] = excl + pre[j];
    }
    if (t == 1023) g_rowptr[NN] = excl + s;
}

__global__ void k_fill(const int* __restrict__ ei) {
    int e = blockIdx.x * blockDim.x + threadIdx.x;
    if (e < EE) {
        int d = clampN(ei[EE + e]);
        int pos = g_rowptr[d] + atomicAdd(&g_cursor[d], 1);
        if (pos >= 0 && pos < EE) {
            g_eids[pos] = e;
            g_esrc[pos] = clampN(ei[e]);
            g_edst[pos] = d;
        }
    }
}

// ---------------- node projections via split-fp16 mma (full 3-term) ----------------
#define XS 17
#define BS2 264

__global__ __launch_bounds__(256) void k_proj_mma(const float* __restrict__ X,
                                                  const float* __restrict__ bl,
                                                  const float* __restrict__ br) {
    __shared__ float    Xs[64 * XS];
    __shared__ uint32_t WB_h[8 * BS2];
    __shared__ uint32_t WB_l[8 * BS2];

    int t = threadIdx.x;
    int lane = t & 31;
    int warp = t >> 5;
    int mt = warp >> 1;
    int ng = warp & 1;
    int grp = lane >> 2;
    int thr = lane & 3;
    int row0 = mt * 16 + grp;
    int bm = blockIdx.x * 64;

#pragma unroll
    for (int w = 0; w < 2; w++) {
        const uint32_t* Whi = g_WB_hi + w * 32768;
        const uint32_t* Wlo = g_WB_lo + w * 32768;
        float acc[16][4];
#pragma unroll
        for (int nt = 0; nt < 16; nt++)
#pragma unroll
            for (int q = 0; q < 4; q++) acc[nt][q] = 0.f;

        for (int kc = 0; kc < 16; kc++) {
            __syncthreads();
#pragma unroll
            for (int r = 0; r < 4; r++) {
                int i = t + r * 256;
                int row = i >> 4, col = i & 15;
                int gr = bm + row;
                Xs[row * XS + col] = (gr < NN) ? X[(size_t)gr * 256 + kc * 16 + col] : 0.f;
            }
#pragma unroll
            for (int r = 0; r < 8; r++) {
                int i = t + r * 256;
                int kk = i >> 8, c = i & 255;
                WB_h[kk * BS2 + c] = Whi[(kc * 8 + kk) * 256 + c];
                WB_l[kk * BS2 + c] = Wlo[(kc * 8 + kk) * 256 + c];
            }
            __syncthreads();

            int cA = thr * 2;
            float x00 = Xs[row0 * XS + cA],           x01 = Xs[row0 * XS + cA + 1];
            float x10 = Xs[(row0 + 8) * XS + cA],     x11 = Xs[(row0 + 8) * XS + cA + 1];
            float x20 = Xs[row0 * XS + cA + 8],       x21 = Xs[row0 * XS + cA + 9];
            float x30 = Xs[(row0 + 8) * XS + cA + 8], x31 = Xs[(row0 + 8) * XS + cA + 9];
            __half h00 = __float2half_rn(x00), h01 = __float2half_rn(x01);
            __half h10 = __float2half_rn(x10), h11 = __float2half_rn(x11);
            __half h20 = __float2half_rn(x20), h21 = __float2half_rn(x21);
            __half h30 = __float2half_rn(x30), h31 = __float2half_rn(x31);
            uint32_t ah0 = pack_h2(__half2float(h00), __half2float(h01));
            uint32_t ah1 = pack_h2(__half2float(h10), __half2float(h11));
            uint32_t ah2 = pack_h2(__half2float(h20), __half2float(h21));
            uint32_t ah3 = pack_h2(__half2float(h30), __half2float(h31));
            uint32_t al0 = pack_h2(x00 - __half2float(h00), x01 - __half2float(h01));
            uint32_t al1 = pack_h2(x10 - __half2float(h10), x11 - __half2float(h11));
            uint32_t al2 = pack_h2(x20 - __half2float(h20), x21 - __half2float(h21));
            uint32_t al3 = pack_h2(x30 - __half2float(h30), x31 - __half2float(h31));

#pragma unroll
            for (int nt = 0; nt < 16; nt++) {
                int ccol = ng * 128 + nt * 8 + grp;
                uint32_t bh0 = WB_h[thr * BS2 + ccol];
                uint32_t bh1 = WB_h[(thr + 4) * BS2 + ccol];
                uint32_t bl0 = WB_l[thr * BS2 + ccol];
                uint32_t bl1 = WB_l[(thr + 4) * BS2 + ccol];
                asm("mma.sync.aligned.m16n8k16.row.col.f32.f16.f16.f32 "
                    "{%0,%1,%2,%3}, {%4,%5,%6,%7}, {%8,%9}, {%0,%1,%2,%3};"
                    : "+f"(acc[nt][0]), "+f"(acc[nt][1]), "+f"(acc[nt][2]), "+f"(acc[nt][3])
                    : "r"(al0), "r"(al1), "r"(al2), "r"(al3), "r"(bh0), "r"(bh1));
                asm("mma.sync.aligned.m16n8k16.row.col.f32.f16.f16.f32 "
                    "{%0,%1,%2,%3}, {%4,%5,%6,%7}, {%8,%9}, {%0,%1,%2,%3};"
                    : "+f"(acc[nt][0]), "+f"(acc[nt][1]), "+f"(acc[nt][2]), "+f"(acc[nt][3])
                    : "r"(ah0), "r"(ah1), "r"(ah2), "r"(ah3), "r"(bl0), "r"(bl1));
                asm("mma.sync.aligned.m16n8k16.row.col.f32.f16.f16.f32 "
                    "{%0,%1,%2,%3}, {%4,%5,%6,%7}, {%8,%9}, {%0,%1,%2,%3};"
                    : "+f"(acc[nt][0]), "+f"(acc[nt][1]), "+f"(acc[nt][2]), "+f"(acc[nt][3])
                    : "r"(ah0), "r"(ah1), "r"(ah2), "r"(ah3), "r"(bh0), "r"(bh1));
            }
        }

        float* out = w ? g_xr : g_xl;
        const float* bb = w ? br : bl;
        int r0 = bm + row0, r1 = bm + row0 + 8;
#pragma unroll
        for (int nt = 0; nt < 16; nt++) {
            int col = ng * 128 + nt * 8 + 2 * thr;
            float v00 = acc[nt][0] + bb[col];
            float v01 = acc[nt][1] + bb[col + 1];
            float v10 = acc[nt][2] + bb[col];
            float v11 = acc[nt][3] + bb[col + 1];
            if (r0 < NN) {
                out[(size_t)r0 * 256 + col]     = v00;
                out[(size_t)r0 * 256 + col + 1] = v01;
                if (w == 0)
                    *(uint32_t*)&g_xl_h[(size_t)r0 * 256 + col] = pack_h2(v00, v01);
            }
            if (r1 < NN) {
                out[(size_t)r1 * 256 + col]     = v10;
                out[(size_t)r1 * 256 + col + 1] = v11;
                if (w == 0)
                    *(uint32_t*)&g_xl_h[(size_t)r1 * 256 + col] = pack_h2(v10, v11);
            }
        }
        __syncthreads();
    }
}

// ---------------- self-loop attr = mean of incoming edge_attr ----------------
__global__ void k_loopattr(const float* __restrict__ ea) {
    int w = blockIdx.x * (blockDim.x >> 5) + (threadIdx.x >> 5);
    int lane = threadIdx.x & 31;
    if (w >= NN) return;
    int start = g_rowptr[w];
    int deg = g_rowptr[w + 1] - start;
    float a0 = 0.f, a1 = 0.f;
    for (int i = 0; i < deg; i++) {
        int e = g_eids[start + i];
        a0 += ea[(size_t)e * 64 + lane];
        a1 += ea[(size_t)e * 64 + 32 + lane];
    }
    float inv = 1.0f / (float)max(deg, 1);
    g_loop_attr[w * 64 + lane] = a0 * inv;
    g_loop_attr[w * 64 + 32 + lane] = a1 * inv;
}

// ---------------- edge logits: persistent blocks, full B resident in smem ----------------
#define EAS 72
#define EPS 68
#define SMEM_LOGITS ((32 * BS2 + 64 * EAS + 256 + 128) * 4)
#define LOGITS_GRID 296

__global__ __launch_bounds__(256) void k_logits_mma(const float* __restrict__ eattr,
                                                    const float* __restrict__ att) {
    extern __shared__ float smem_dyn[];
    uint32_t* B_s   = (uint32_t*)smem_dyn;          // 32*BS2
    float*    EA_s  = smem_dyn + 32 * BS2;          // 64*EAS (doubles as EP)
    float*    att_s = EA_s + 64 * EAS;              // 256
    int*      s_src = (int*)(att_s + 256);          // 64
    int*      s_dst = s_src + 64;                   // 64
    float*    EP_s  = EA_s;

    int t = threadIdx.x;
    int lane = t & 31;
    int warp = t >> 5;
    int mt = warp >> 1;
    int ng = warp & 1;
    int grp = lane >> 2;
    int thr = lane & 3;
    int row0 = mt * 16 + grp;

    att_s[t] = att[t];
#pragma unroll
    for (int r = 0; r < 32; r++) {
        int i = t + r * 256;
        int kk = i >> 8, c = i & 255;
        B_s[kk * BS2 + c] = g_WeB_hi[i];
    }

    for (int tile = blockIdx.x; tile < NTILES; tile += LOGITS_GRID) {
        int base = tile * 64;
        if (base > TOT - 64) base = TOT - 64;   // tail overlap: identical stores

        __syncthreads();                         // prior epilogue done before overwrite
        if (t < 64) {
            int p = base + t;
            int s, d;
            if (p < EE) { s = g_esrc[p]; d = g_edst[p]; }
            else { s = p - EE; d = p - EE; }
            s_src[t] = s; s_dst[t] = d;
        }
        {
            int el = t >> 2, part = t & 3;
            int p = base + el;
            const float* a;
            if (p < EE) a = eattr + (size_t)g_eids[p] * 64;
            else        a = g_loop_attr + (size_t)(p - EE) * 64;
            float* q = &EA_s[el * EAS + part * 16];
#pragma unroll
            for (int r = 0; r < 4; r++)
                *(float4*)(q + r * 4) = *(const float4*)&a[part * 16 + r * 4];
        }
        __syncthreads();

        float acc[4][4][4];
#pragma unroll
        for (int qq = 0; qq < 4; qq++)
#pragma unroll
            for (int nt = 0; nt < 4; nt++)
#pragma unroll
                for (int q = 0; q < 4; q++) acc[qq][nt][q] = 0.f;

#pragma unroll
        for (int kc = 0; kc < 4; kc++) {
            int cA = kc * 16 + thr * 2;
            float x00 = EA_s[row0 * EAS + cA],           x01 = EA_s[row0 * EAS + cA + 1];
            float x10 = EA_s[(row0 + 8) * EAS + cA],     x11 = EA_s[(row0 + 8) * EAS + cA + 1];
            float x20 = EA_s[row0 * EAS + cA + 8],       x21 = EA_s[row0 * EAS + cA + 9];
            float x30 = EA_s[(row0 + 8) * EAS + cA + 8], x31 = EA_s[(row0 + 8) * EAS + cA + 9];
            __half h00 = __float2half_rn(x00), h01 = __float2half_rn(x01);
            __half h10 = __float2half_rn(x10), h11 = __float2half_rn(x11);
            __half h20 = __float2half_rn(x20), h21 = __float2half_rn(x21);
            __half h30 = __float2half_rn(x30), h31 = __float2half_rn(x31);
            uint32_t ah0 = pack_h2(__half2float(h00), __half2float(h01));
            uint32_t ah1 = pack_h2(__half2float(h10), __half2float(h11));
            uint32_t ah2 = pack_h2(__half2float(h20), __half2float(h21));
            uint32_t ah3 = pack_h2(__half2float(h30), __half2float(h31));
            uint32_t al0 = pack_h2(x00 - __half2float(h00), x01 - __half2float(h01));
            uint32_t al1 = pack_h2(x10 - __half2float(h10), x11 - __half2float(h11));
            uint32_t al2 = pack_h2(x20 - __half2float(h20), x21 - __half2float(h21));
            uint32_t al3 = pack_h2(x30 - __half2float(h30), x31 - __half2float(h31));

            int rb0 = (kc * 8 + thr) * BS2;
            int rb1 = (kc * 8 + thr + 4) * BS2;
#pragma unroll
            for (int qq = 0; qq < 4; qq++) {
#pragma unroll
                for (int nt = 0; nt < 4; nt++) {
                    int ccol = qq * 64 + ng * 32 + nt * 8 + grp;
                    uint32_t bh0 = B_s[rb0 + ccol];
                    uint32_t bh1 = B_s[rb1 + ccol];
                    asm("mma.sync.aligned.m16n8k16.row.col.f32.f16.f16.f32 "
                        "{%0,%1,%2,%3}, {%4,%5,%6,%7}, {%8,%9}, {%0,%1,%2,%3};"
                        : "+f"(acc[qq][nt][0]), "+f"(acc[qq][nt][1]), "+f"(acc[qq][nt][2]), "+f"(acc[qq][nt][3])
                        : "r"(al0), "r"(al1), "r"(al2), "r"(al3), "r"(bh0), "r"(bh1));
                    asm("mma.sync.aligned.m16n8k16.row.col.f32.f16.f16.f32 "
                        "{%0,%1,%2,%3}, {%4,%5,%6,%7}, {%8,%9}, {%0,%1,%2,%3};"
                        : "+f"(acc[qq][nt][0]), "+f"(acc[qq][nt][1]), "+f"(acc[qq][nt][2]), "+f"(acc[qq][nt][3])
                        : "r"(ah0), "r"(ah1), "r"(ah2), "r"(ah3), "r"(bh0), "r"(bh1));
                }
            }
        }

#pragma unroll
        for (int quarter = 0; quarter < 4; quarter++) {
            __syncthreads();
#pragma unroll
            for (int nt = 0; nt < 4; nt++) {
                int cb = ng * 32 + nt * 8 + 2 * thr;
                EP_s[row0 * EPS + cb]           = acc[quarter][nt][0];
                EP_s[row0 * EPS + cb + 1]       = acc[quarter][nt][1];
                EP_s[(row0 + 8) * EPS + cb]     = acc[quarter][nt][2];
                EP_s[(row0 + 8) * EPS + cb + 1] = acc[quarter][nt][3];
            }
            __syncthreads();
            {
                int el = t >> 2, sub = t & 3;
                int c0 = sub * 16;
                int src = s_src[el], dst = s_dst[el];
                const float* xlp = g_xl + (size_t)src * 256 + quarter * 64 + c0;
                const float* xrp = g_xr + (size_t)dst * 256 + quarter * 64 + c0;
                const float* epp = &EP_s[el * EPS + c0];
                const float* ats = &att_s[quarter * 64 + c0];
                float s = 0.f;
#pragma unroll
                for (int q4 = 0; q4 < 4; q4++) {
                    float4 ev = *(const float4*)&epp[q4 * 4];
                    float4 lv = *(const float4*)&xlp[q4 * 4];
                    float4 rv = *(const float4*)&xrp[q4 * 4];
                    float4 av = *(const float4*)&ats[q4 * 4];
                    float m0 = ev.x + lv.x + rv.x; m0 = (m0 >= 0.f) ? m0 : 0.2f * m0;
                    float m1 = ev.y + lv.y + rv.y; m1 = (m1 >= 0.f) ? m1 : 0.2f * m1;
                    float m2 = ev.z + lv.z + rv.z; m2 = (m2 >= 0.f) ? m2 : 0.2f * m2;
                    float m3 = ev.w + lv.w + rv.w; m3 = (m3 >= 0.f) ? m3 : 0.2f * m3;
                    s = fmaf(m0, av.x, s); s = fmaf(m1, av.y, s);
                    s = fmaf(m2, av.z, s); s = fmaf(m3, av.w, s);
                }
                s += __shfl_xor_sync(FULLMASK, s, 1);
                s += __shfl_xor_sync(FULLMASK, s, 2);
                if (sub == 0)
                    g_logits[(size_t)(base + el) * 4 + quarter] = s;
            }
        }
    }
}

// ---------------- per-node softmax + aggregation + SiLU + LayerNorm + alpha out ----------------
__global__ void k_node(const float* __restrict__ bias,
                       const float* __restrict__ gamma, const float* __restrict__ beta,
                       float* __restrict__ out_h, float* __restrict__ out_alpha) {
    __shared__ float red[256];
    __shared__ float s_inv[4];
    __shared__ float s_alpha[64 * 4];
    __shared__ int   s_srcs[64];
    __shared__ float s_mu, s_var;
    int n = blockIdx.x, t = threadIdx.x;
    int start = g_rowptr[n];
    int deg = g_rowptr[n + 1] - start;
    int cnt = deg + 1;
    int h4 = t & 3;

    float ls = 0.f;
    for (int i = t >> 2; i < cnt; i += 64) {
        int p = (i < deg) ? (start + i) : (EE + n);
        ls += __expf(g_logits[(size_t)p * 4 + h4]);
    }
    red[t] = ls;
    __syncthreads();
    if (t < 4) {
        float sum = 0.f;
        for (int j = t; j < 256; j += 4) sum += red[j];
        s_inv[t] = 1.0f / sum;
    }
    __syncthreads();

    int c = t, hh = c >> 6;
    float acc = 0.f;
    for (int bb = 0; bb < cnt; bb += 64) {
        int m = min(64, cnt - bb);
        __syncthreads();
        if (t < m) {
            int i = bb + t;
            int p = (i < deg) ? (start + i) : (EE + n);
            int e = (i < deg) ? g_eids[p] : (EE + n);
            s_srcs[t] = (i < deg) ? g_esrc[p] : n;
            float4 lg = *(const float4*)&g_logits[(size_t)p * 4];
            float a0 = __expf(lg.x) * s_inv[0];
            float a1 = __expf(lg.y) * s_inv[1];
            float a2 = __expf(lg.z) * s_inv[2];
            float a3 = __expf(lg.w) * s_inv[3];
            s_alpha[t * 4 + 0] = a0;
            s_alpha[t * 4 + 1] = a1;
            s_alpha[t * 4 + 2] = a2;
            s_alpha[t * 4 + 3] = a3;
            *(float4*)&out_alpha[(size_t)e * 4] = make_float4(a0, a1, a2, a3);
        }
        __syncthreads();
        for (int i = 0; i < m; i++)
            acc = fmaf(s_alpha[i * 4 + hh],
                       __half2float(g_xl_h[(size_t)s_srcs[i] * 256 + c]), acc);
    }

    float v = acc + bias[c];
    v = v / (1.0f + __expf(-v));   // SiLU
    __syncthreads();
    red[t] = v;
    __syncthreads();
    for (int s = 128; s > 0; s >>= 1) { if (t < s) red[t] += red[t + s]; __syncthreads(); }
    if (t == 0) s_mu = red[0] * (1.0f / 256.0f);
    __syncthreads();
    float d = v - s_mu;
    red[t] = d * d;
    __syncthreads();
    for (int s = 128; s > 0; s >>= 1) { if (t < s) red[t] += red[t + s]; __syncthreads(); }
    if (t == 0) s_var = red[0] * (1.0f / 256.0f);
    __syncthreads();
    out_h[(size_t)n * 256 + c] = d * rsqrtf(s_var + 1e-5f) * gamma[c] + beta[c];
}

// ---------------- launch: fork-join overlap of CSR chain and projection GEMM ----------------
extern "C" void kernel_launch(void* const* d_in, const int* in_sizes, int n_in,
                              void* d_out, int out_size) {
    const float* x     = (const float*)d_in[0];
    const int*   ei    = (const int*)d_in[1];     // int32 (JAX x64-disabled)
    const float* eattr = (const float*)d_in[2];
    const float* Wl    = (const float*)d_in[3];
    const float* bl    = (const float*)d_in[4];
    const float* Wr    = (const float*)d_in[5];
    const float* br    = (const float*)d_in[6];
    const float* We    = (const float*)d_in[7];
    const float* att   = (const float*)d_in[8];
    const float* bias  = (const float*)d_in[9];
    const float* gamma = (const float*)d_in[10];
    const float* beta  = (const float*)d_in[11];

    float* out_h = (float*)d_out;
    float* out_alpha = out_h + (size_t)NN * HCv;

    static bool attr_done = false;
    if (!attr_done) {
        cudaFuncSetAttribute(k_logits_mma, cudaFuncAttributeMaxDynamicSharedMemorySize,
                             SMEM_LOGITS);
        attr_done = true;
    }

    cudaStream_t s2 = 0;
    cudaEvent_t ev0 = 0, ev1 = 0;
    bool forked = (cudaStreamCreateWithFlags(&s2, cudaStreamNonBlocking) == cudaSuccess) &&
                  (cudaEventCreateWithFlags(&ev0, cudaEventDisableTiming) == cudaSuccess) &&
                  (cudaEventCreateWithFlags(&ev1, cudaEventDisableTiming) == cudaSuccess);

    k_initA<<<40, 256>>>(We);

    if (forked) {
        cudaEventRecord(ev0, 0);
        cudaStreamWaitEvent(s2, ev0, 0);
        k_initB<<<256, 256, 0, s2>>>(Wl, Wr);
        k_proj_mma<<<(NN + 63) / 64, 256, 0, s2>>>(x, bl, br);
        cudaEventRecord(ev1, s2);
    } else {
        k_initB<<<256, 256>>>(Wl, Wr);
        k_proj_mma<<<(NN + 63) / 64, 256>>>(x, bl, br);
    }

    k_count<<<(EE + 255) / 256, 256>>>(ei);
    k_scan<<<1, 1024>>>();
    k_fill<<<(EE + 255) / 256, 256>>>(ei);
    k_loopattr<<<(NN + 7) / 8, 256>>>(eattr);

    if (forked) cudaStreamWaitEvent(0, ev1, 0);     // logits needs xl/xr

    k_logits_mma<<<LOGITS_GRID, 256, SMEM_LOGITS>>>(eattr, att);
    k_node<<<NN, 256>>>(bias, gamma, beta, out_h, out_alpha);
}

// round 17
// speedup vs baseline: 1.0647x; 1.0647x over previous
#include <cuda_runtime.h>
#include <cuda_fp16.h>
#include <cstdint>

#define NN 10000
#define EE 320000
#define HCv 256
#define EDv 64
#define TOT (EE + NN)
#define NTILES ((TOT + 63) / 64)
#define FULLMASK 0xffffffffu

static __device__ __forceinline__ int clampN(int v) {
    v = v < 0 ? 0 : v;
    return v > (NN - 1) ? (NN - 1) : v;
}

static __device__ __forceinline__ uint32_t pack_h2(float x, float y) {
    __half2 h = __floats2half2_rn(x, y);
    return *(uint32_t*)&h;
}

// ---------------- scratch (device globals; no allocations allowed) ----------------
static __device__ float    g_xl[NN * HCv];
static __device__ float    g_xr[NN * HCv];
static __device__ float    g_logits[TOT * 4];         // indexed by CSR position
static __device__ float    g_loop_attr[NN * EDv];
static __device__ uint32_t g_WeB_hi[32 * HCv];        // We fp16 (1-term fp16 mma in logits)
static __device__ uint32_t g_WB_hi[2 * 128 * HCv];
static __device__ uint32_t g_WB_lo[2 * 128 * HCv];
static __device__ int      g_deg[NN];
static __device__ int      g_rowptr[NN + 1];
static __device__ int      g_cursor[NN];
static __device__ int      g_eids[EE];                // CSR pos -> original edge id
static __device__ int      g_esrc[EE];                // CSR pos -> src node
static __device__ int      g_edst[EE];                // CSR pos -> dst node

// ---------------- initA: CSR init + We pack (main stream) ----------------
__global__ void k_initA(const float* __restrict__ We) {
    int i = blockIdx.x * blockDim.x + threadIdx.x;
    if (i < NN) { g_deg[i] = 0; g_cursor[i] = 0; }
    if (i < 32 * HCv) {
        int c = i & 255, k2 = i >> 8;
        float v0 = We[c * 64 + 2 * k2];
        float v1 = We[c * 64 + 2 * k2 + 1];
        g_WeB_hi[k2 * 256 + c] = pack_h2(v0, v1);
    }
}

// ---------------- initB: Wl/Wr pack (forked stream, feeds k_proj_mma) ----------------
__global__ void k_initB(const float* __restrict__ Wl, const float* __restrict__ Wr) {
    int i = blockIdx.x * blockDim.x + threadIdx.x;
    if (i < 2 * 128 * HCv) {
        int w = i >> 15;
        int rem = i & 32767;
        int c = rem & 255, k2 = rem >> 8;
        const float* W = w ? Wr : Wl;
        float v0 = W[c * 256 + 2 * k2];
        float v1 = W[c * 256 + 2 * k2 + 1];
        __half h0 = __float2half_rn(v0), h1 = __float2half_rn(v1);
        g_WB_hi[i] = pack_h2(__half2float(h0), __half2float(h1));
        g_WB_lo[i] = pack_h2(v0 - __half2float(h0), v1 - __half2float(h1));
    }
}

__global__ void k_count(const int* __restrict__ ei) {
    int e = blockIdx.x * blockDim.x + threadIdx.x;
    if (e < EE) atomicAdd(&g_deg[clampN(ei[EE + e])], 1);
}

__global__ void k_scan() {
    __shared__ int part[1024];
    int t = threadIdx.x;
    int base = t * 10;
    int pre[10];
    int s = 0;
#pragma unroll
    for (int j = 0; j < 10; j++) {
        int idx = base + j;
        int v = (idx < NN) ? g_deg[idx] : 0;
        pre[j] = s;
        s += v;
    }
    part[t] = s;
    __syncthreads();
    for (int off = 1; off < 1024; off <<= 1) {
        int y = (t >= off) ? part[t - off] : 0;
        __syncthreads();
        part[t] += y;
        __syncthreads();
    }
    int excl = (t == 0) ? 0 : part[t - 1];
#pragma unroll
    for (int j = 0; j < 10; j++) {
        int idx = base + j;
        if (idx < NN) g_rowptr[idx] = excl + pre[j];
    }
    if (t == 1023) g_rowptr[NN] = excl + s;
}

__global__ void k_fill(const int* __restrict__ ei) {
    int e = blockIdx.x * blockDim.x + threadIdx.x;
    if (e < EE) {
        int d = clampN(ei[EE + e]);
        int pos = g_rowptr[d] + atomicAdd(&g_cursor[d], 1);
        if (pos >= 0 && pos < EE) {
            g_eids[pos] = e;
            g_esrc[pos] = clampN(ei[e]);
            g_edst[pos] = d;
        }
    }
}

// ---------------- node projections via split-fp16 mma (full 3-term) ----------------
#define XS 17
#define BS2 264

__global__ __launch_bounds__(256) void k_proj_mma(const float* __restrict__ X,
                                                  const float* __restrict__ bl,
                                                  const float* __restrict__ br) {
    __shared__ float    Xs[64 * XS];
    __shared__ uint32_t WB_h[8 * BS2];
    __shared__ uint32_t WB_l[8 * BS2];

    int t = threadIdx.x;
    int lane = t & 31;
    int warp = t >> 5;
    int mt = warp >> 1;
    int ng = warp & 1;
    int grp = lane >> 2;
    int thr = lane & 3;
    int row0 = mt * 16 + grp;
    int bm = blockIdx.x * 64;

#pragma unroll
    for (int w = 0; w < 2; w++) {
        const uint32_t* Whi = g_WB_hi + w * 32768;
        const uint32_t* Wlo = g_WB_lo + w * 32768;
        float acc[16][4];
#pragma unroll
        for (int nt = 0; nt < 16; nt++)
#pragma unroll
            for (int q = 0; q < 4; q++) acc[nt][q] = 0.f;

        for (int kc = 0; kc < 16; kc++) {
            __syncthreads();
#pragma unroll
            for (int r = 0; r < 4; r++) {
                int i = t + r * 256;
                int row = i >> 4, col = i & 15;
                int gr = bm + row;
                Xs[row * XS + col] = (gr < NN) ? X[(size_t)gr * 256 + kc * 16 + col] : 0.f;
            }
#pragma unroll
            for (int r = 0; r < 8; r++) {
                int i = t + r * 256;
                int kk = i >> 8, c = i & 255;
                WB_h[kk * BS2 + c] = Whi[(kc * 8 + kk) * 256 + c];
                WB_l[kk * BS2 + c] = Wlo[(kc * 8 + kk) * 256 + c];
            }
            __syncthreads();

            int cA = thr * 2;
            float x00 = Xs[row0 * XS + cA],           x01 = Xs[row0 * XS + cA + 1];
            float x10 = Xs[(row0 + 8) * XS + cA],     x11 = Xs[(row0 + 8) * XS + cA + 1];
            float x20 = Xs[row0 * XS + cA + 8],       x21 = Xs[row0 * XS + cA + 9];
            float x30 = Xs[(row0 + 8) * XS + cA + 8], x31 = Xs[(row0 + 8) * XS + cA + 9];
            __half h00 = __float2half_rn(x00), h01 = __float2half_rn(x01);
            __half h10 = __float2half_rn(x10), h11 = __float2half_rn(x11);
            __half h20 = __float2half_rn(x20), h21 = __float2half_rn(x21);
            __half h30 = __float2half_rn(x30), h31 = __float2half_rn(x31);
            uint32_t ah0 = pack_h2(__half2float(h00), __half2float(h01));
            uint32_t ah1 = pack_h2(__half2float(h10), __half2float(h11));
            uint32_t ah2 = pack_h2(__half2float(h20), __half2float(h21));
            uint32_t ah3 = pack_h2(__half2float(h30), __half2float(h31));
            uint32_t al0 = pack_h2(x00 - __half2float(h00), x01 - __half2float(h01));
            uint32_t al1 = pack_h2(x10 - __half2float(h10), x11 - __half2float(h11));
            uint32_t al2 = pack_h2(x20 - __half2float(h20), x21 - __half2float(h21));
            uint32_t al3 = pack_h2(x30 - __half2float(h30), x31 - __half2float(h31));

#pragma unroll
            for (int nt = 0; nt < 16; nt++) {
                int ccol = ng * 128 + nt * 8 + grp;
                uint32_t bh0 = WB_h[thr * BS2 + ccol];
                uint32_t bh1 = WB_h[(thr + 4) * BS2 + ccol];
                uint32_t bl0 = WB_l[thr * BS2 + ccol];
                uint32_t bl1 = WB_l[(thr + 4) * BS2 + ccol];
                asm("mma.sync.aligned.m16n8k16.row.col.f32.f16.f16.f32 "
                    "{%0,%1,%2,%3}, {%4,%5,%6,%7}, {%8,%9}, {%0,%1,%2,%3};"
                    : "+f"(acc[nt][0]), "+f"(acc[nt][1]), "+f"(acc[nt][2]), "+f"(acc[nt][3])
                    : "r"(al0), "r"(al1), "r"(al2), "r"(al3), "r"(bh0), "r"(bh1));
                asm("mma.sync.aligned.m16n8k16.row.col.f32.f16.f16.f32 "
                    "{%0,%1,%2,%3}, {%4,%5,%6,%7}, {%8,%9}, {%0,%1,%2,%3};"
                    : "+f"(acc[nt][0]), "+f"(acc[nt][1]), "+f"(acc[nt][2]), "+f"(acc[nt][3])
                    : "r"(ah0), "r"(ah1), "r"(ah2), "r"(ah3), "r"(bl0), "r"(bl1));
                asm("mma.sync.aligned.m16n8k16.row.col.f32.f16.f16.f32 "
                    "{%0,%1,%2,%3}, {%4,%5,%6,%7}, {%8,%9}, {%0,%1,%2,%3};"
                    : "+f"(acc[nt][0]), "+f"(acc[nt][1]), "+f"(acc[nt][2]), "+f"(acc[nt][3])
                    : "r"(ah0), "r"(ah1), "r"(ah2), "r"(ah3), "r"(bh0), "r"(bh1));
            }
        }

        float* out = w ? g_xr : g_xl;
        const float* bb = w ? br : bl;
        int r0 = bm + row0, r1 = bm + row0 + 8;
#pragma unroll
        for (int nt = 0; nt < 16; nt++) {
            int col = ng * 128 + nt * 8 + 2 * thr;
            if (r0 < NN) {
                out[(size_t)r0 * 256 + col]     = acc[nt][0] + bb[col];
                out[(size_t)r0 * 256 + col + 1] = acc[nt][1] + bb[col + 1];
            }
            if (r1 < NN) {
                out[(size_t)r1 * 256 + col]     = acc[nt][2] + bb[col];
                out[(size_t)r1 * 256 + col + 1] = acc[nt][3] + bb[col + 1];
            }
        }
        __syncthreads();
    }
}

// ---------------- self-loop attr = mean of incoming edge_attr ----------------
__global__ void k_loopattr(const float* __restrict__ ea) {
    int w = blockIdx.x * (blockDim.x >> 5) + (threadIdx.x >> 5);
    int lane = threadIdx.x & 31;
    if (w >= NN) return;
    int start = g_rowptr[w];
    int deg = g_rowptr[w + 1] - start;
    float a0 = 0.f, a1 = 0.f;
    for (int i = 0; i < deg; i++) {
        int e = g_eids[start + i];
        a0 += ea[(size_t)e * 64 + lane];
        a1 += ea[(size_t)e * 64 + 32 + lane];
    }
    float inv = 1.0f / (float)max(deg, 1);
    g_loop_attr[w * 64 + lane] = a0 * inv;
    g_loop_attr[w * 64 + 32 + lane] = a1 * inv;
}

// ---------------- edge logits: persistent blocks, full B resident, 1-term fp16 mma ----------------
#define EAS 72
#define EPS 68
#define SMEM_LOGITS ((32 * BS2 + 64 * EAS + 256 + 128) * 4)
#define LOGITS_GRID 296

__global__ __launch_bounds__(256) void k_logits_mma(const float* __restrict__ eattr,
                                                    const float* __restrict__ att) {
    extern __shared__ float smem_dyn[];
    uint32_t* B_s   = (uint32_t*)smem_dyn;          // 32*BS2
    float*    EA_s  = smem_dyn + 32 * BS2;          // 64*EAS (doubles as EP)
    float*    att_s = EA_s + 64 * EAS;              // 256
    int*      s_src = (int*)(att_s + 256);          // 64
    int*      s_dst = s_src + 64;                   // 64
    float*    EP_s  = EA_s;

    int t = threadIdx.x;
    int lane = t & 31;
    int warp = t >> 5;
    int mt = warp >> 1;
    int ng = warp & 1;
    int grp = lane >> 2;
    int thr = lane & 3;
    int row0 = mt * 16 + grp;

    att_s[t] = att[t];
#pragma unroll
    for (int r = 0; r < 32; r++) {
        int i = t + r * 256;
        int kk = i >> 8, c = i & 255;
        B_s[kk * BS2 + c] = g_WeB_hi[i];
    }

    for (int tile = blockIdx.x; tile < NTILES; tile += LOGITS_GRID) {
        int base = tile * 64;
        if (base > TOT - 64) base = TOT - 64;   // tail overlap: identical stores

        __syncthreads();                         // prior epilogue done before overwrite
        if (t < 64) {
            int p = base + t;
            int s, d;
            if (p < EE) { s = g_esrc[p]; d = g_edst[p]; }
            else { s = p - EE; d = p - EE; }
            s_src[t] = s; s_dst[t] = d;
        }
        {
            int el = t >> 2, part = t & 3;
            int p = base + el;
            const float* a;
            if (p < EE) a = eattr + (size_t)g_eids[p] * 64;
            else        a = g_loop_attr + (size_t)(p - EE) * 64;
            float* q = &EA_s[el * EAS + part * 16];
#pragma unroll
            for (int r = 0; r < 4; r++)
                *(float4*)(q + r * 4) = *(const float4*)&a[part * 16 + r * 4];
        }
        __syncthreads();

        float acc[4][4][4];
#pragma unroll
        for (int qq = 0; qq < 4; qq++)
#pragma unroll
            for (int nt = 0; nt < 4; nt++)
#pragma unroll
                for (int q = 0; q < 4; q++) acc[qq][nt][q] = 0.f;

#pragma unroll
        for (int kc = 0; kc < 4; kc++) {
            int cA = kc * 16 + thr * 2;
            uint32_t ah0 = pack_h2(EA_s[row0 * EAS + cA],           EA_s[row0 * EAS + cA + 1]);
            uint32_t ah1 = pack_h2(EA_s[(row0 + 8) * EAS + cA],     EA_s[(row0 + 8) * EAS + cA + 1]);
            uint32_t ah2 = pack_h2(EA_s[row0 * EAS + cA + 8],       EA_s[row0 * EAS + cA + 9]);
            uint32_t ah3 = pack_h2(EA_s[(row0 + 8) * EAS + cA + 8], EA_s[(row0 + 8) * EAS + cA + 9]);

            int rb0 = (kc * 8 + thr) * BS2;
            int rb1 = (kc * 8 + thr + 4) * BS2;
#pragma unroll
            for (int qq = 0; qq < 4; qq++) {
#pragma unroll
                for (int nt = 0; nt < 4; nt++) {
                    int ccol = qq * 64 + ng * 32 + nt * 8 + grp;
                    uint32_t bh0 = B_s[rb0 + ccol];
                    uint32_t bh1 = B_s[rb1 + ccol];
                    asm("mma.sync.aligned.m16n8k16.row.col.f32.f16.f16.f32 "
                        "{%0,%1,%2,%3}, {%4,%5,%6,%7}, {%8,%9}, {%0,%1,%2,%3};"
                        : "+f"(acc[qq][nt][0]), "+f"(acc[qq][nt][1]), "+f"(acc[qq][nt][2]), "+f"(acc[qq][nt][3])
                        : "r"(ah0), "r"(ah1), "r"(ah2), "r"(ah3), "r"(bh0), "r"(bh1));
                }
            }
        }

#pragma unroll
        for (int quarter = 0; quarter < 4; quarter++) {
            __syncthreads();
#pragma unroll
            for (int nt = 0; nt < 4; nt++) {
                int cb = ng * 32 + nt * 8 + 2 * thr;
                EP_s[row0 * EPS + cb]           = acc[quarter][nt][0];
                EP_s[row0 * EPS + cb + 1]       = acc[quarter][nt][1];
                EP_s[(row0 + 8) * EPS + cb]     = acc[quarter][nt][2];
                EP_s[(row0 + 8) * EPS + cb + 1] = acc[quarter][nt][3];
            }
            __syncthreads();
            {
                int el = t >> 2, sub = t & 3;
                int c0 = sub * 16;
                int src = s_src[el], dst = s_dst[el];
                const float* xlp = g_xl + (size_t)src * 256 + quarter * 64 + c0;
                const float* xrp = g_xr + (size_t)dst * 256 + quarter * 64 + c0;
                const float* epp = &EP_s[el * EPS + c0];
                const float* ats = &att_s[quarter * 64 + c0];
                float s = 0.f;
#pragma unroll
                for (int q4 = 0; q4 < 4; q4++) {
                    float4 ev = *(const float4*)&epp[q4 * 4];
                    float4 lv = *(const float4*)&xlp[q4 * 4];
                    float4 rv = *(const float4*)&xrp[q4 * 4];
                    float4 av = *(const float4*)&ats[q4 * 4];
                    float m0 = ev.x + lv.x + rv.x; m0 = (m0 >= 0.f) ? m0 : 0.2f * m0;
                    float m1 = ev.y + lv.y + rv.y; m1 = (m1 >= 0.f) ? m1 : 0.2f * m1;
                    float m2 = ev.z + lv.z + rv.z; m2 = (m2 >= 0.f) ? m2 : 0.2f * m2;
                    float m3 = ev.w + lv.w + rv.w; m3 = (m3 >= 0.f) ? m3 : 0.2f * m3;
                    s = fmaf(m0, av.x, s); s = fmaf(m1, av.y, s);
                    s = fmaf(m2, av.z, s); s = fmaf(m3, av.w, s);
                }
                s += __shfl_xor_sync(FULLMASK, s, 1);
                s += __shfl_xor_sync(FULLMASK, s, 2);
                if (sub == 0)
                    g_logits[(size_t)(base + el) * 4 + quarter] = s;
            }
        }
    }
}

// ---------------- per-node softmax + aggregation + SiLU + LayerNorm + alpha out ----------------
__global__ void k_node(const float* __restrict__ bias,
                       const float* __restrict__ gamma, const float* __restrict__ beta,
                       float* __restrict__ out_h, float* __restrict__ out_alpha) {
    __shared__ float red[256];
    __shared__ float s_inv[4];
    __shared__ float s_alpha[64 * 4];
    __shared__ int   s_srcs[64];
    __shared__ float s_mu, s_var;
    int n = blockIdx.x, t = threadIdx.x;
    int lane = t & 31, wid = t >> 5;
    int start = g_rowptr[n];
    int deg = g_rowptr[n + 1] - start;
    int cnt = deg + 1;
    int h4 = t & 3;

    float ls = 0.f;
    for (int i = t >> 2; i < cnt; i += 64) {
        int p = (i < deg) ? (start + i) : (EE + n);
        ls += __expf(g_logits[(size_t)p * 4 + h4]);
    }
    red[t] = ls;
    __syncthreads();
    if (t < 4) {
        float sum = 0.f;
        for (int j = t; j < 256; j += 4) sum += red[j];
        s_inv[t] = 1.0f / sum;
    }
    __syncthreads();

    int c = t, hh = c >> 6;
    float acc = 0.f;
    for (int bb = 0; bb < cnt; bb += 64) {
        int m = min(64, cnt - bb);
        __syncthreads();
        if (t < m) {
            int i = bb + t;
            int p = (i < deg) ? (start + i) : (EE + n);
            int e = (i < deg) ? g_eids[p] : (EE + n);
            s_srcs[t] = (i < deg) ? g_esrc[p] : n;
            float4 lg = *(const float4*)&g_logits[(size_t)p * 4];
            float a0 = __expf(lg.x) * s_inv[0];
            float a1 = __expf(lg.y) * s_inv[1];
            float a2 = __expf(lg.z) * s_inv[2];
            float a3 = __expf(lg.w) * s_inv[3];
            s_alpha[t * 4 + 0] = a0;
            s_alpha[t * 4 + 1] = a1;
            s_alpha[t * 4 + 2] = a2;
            s_alpha[t * 4 + 3] = a3;
            *(float4*)&out_alpha[(size_t)e * 4] = make_float4(a0, a1, a2, a3);
        }
        __syncthreads();
        for (int i = 0; i < m; i++)
            acc = fmaf(s_alpha[i * 4 + hh], g_xl[(size_t)s_srcs[i] * 256 + c], acc);
    }

    float v = acc + bias[c];
    v = v / (1.0f + __expf(-v));   // SiLU
    __syncthreads();   // s_alpha/red reuse safety

    // LayerNorm via warp shuffles (4 syncs total)
    float wv = v;
#pragma unroll
    for (int o = 16; o; o >>= 1) wv += __shfl_xor_sync(FULLMASK, wv, o);
    if (lane == 0) red[wid] = wv;
    __syncthreads();
    if (t == 0) {
        float s = 0.f;
#pragma unroll
        for (int j = 0; j < 8; j++) s += red[j];
        s_mu = s * (1.0f / 256.0f);
    }
    __syncthreads();
    float d = v - s_mu;
    float wd = d * d;
#pragma unroll
    for (int o = 16; o; o >>= 1) wd += __shfl_xor_sync(FULLMASK, wd, o);
    if (lane == 0) red[wid] = wd;
    __syncthreads();
    if (t == 0) {
        float s = 0.f;
#pragma unroll
        for (int j = 0; j < 8; j++) s += red[j];
        s_var = s * (1.0f / 256.0f);
    }
    __syncthreads();
    out_h[(size_t)n * 256 + c] = d * rsqrtf(s_var + 1e-5f) * gamma[c] + beta[c];
}

// ---------------- launch: fork-join overlap of CSR chain and projection GEMM ----------------
extern "C" void kernel_launch(void* const* d_in, const int* in_sizes, int n_in,
                              void* d_out, int out_size) {
    const float* x     = (const float*)d_in[0];
    const int*   ei    = (const int*)d_in[1];     // int32 (JAX x64-disabled)
    const float* eattr = (const float*)d_in[2];
    const float* Wl    = (const float*)d_in[3];
    const float* bl    = (const float*)d_in[4];
    const float* Wr    = (const float*)d_in[5];
    const float* br    = (const float*)d_in[6];
    const float* We    = (const float*)d_in[7];
    const float* att   = (const float*)d_in[8];
    const float* bias  = (const float*)d_in[9];
    const float* gamma = (const float*)d_in[10];
    const float* beta  = (const float*)d_in[11];

    float* out_h = (float*)d_out;
    float* out_alpha = out_h + (size_t)NN * HCv;

    static bool attr_done = false;
    if (!attr_done) {
        cudaFuncSetAttribute(k_logits_mma, cudaFuncAttributeMaxDynamicSharedMemorySize,
                             SMEM_LOGITS);
        attr_done = true;
    }

    cudaStream_t s2 = 0;
    cudaEvent_t ev0 = 0, ev1 = 0;
    bool forked = (cudaStreamCreateWithFlags(&s2, cudaStreamNonBlocking) == cudaSuccess) &&
                  (cudaEventCreateWithFlags(&ev0, cudaEventDisableTiming) == cudaSuccess) &&
                  (cudaEventCreateWithFlags(&ev1, cudaEventDisableTiming) == cudaSuccess);

    k_initA<<<40, 256>>>(We);

    if (forked) {
        cudaEventRecord(ev0, 0);
        cudaStreamWaitEvent(s2, ev0, 0);
        k_initB<<<256, 256, 0, s2>>>(Wl, Wr);
        k_proj_mma<<<(NN + 63) / 64, 256, 0, s2>>>(x, bl, br);
        cudaEventRecord(ev1, s2);
    } else {
        k_initB<<<256, 256>>>(Wl, Wr);
        k_proj_mma<<<(NN + 63) / 64, 256>>>(x, bl, br);
    }

    k_count<<<(EE + 255) / 256, 256>>>(ei);
    k_scan<<<1, 1024>>>();
    k_fill<<<(EE + 255) / 256, 256>>>(ei);
    k_loopattr<<<(NN + 7) / 8, 256>>>(eattr);

    if (forked) cudaStreamWaitEvent(0, ev1, 0);     // logits needs xl/xr

    k_logits_mma<<<LOGITS_GRID, 256, SMEM_LOGITS>>>(eattr, att);
    k_node<<<NN, 256>>>(bias, gamma, beta, out_h, out_alpha);
}